// round 2
// baseline (speedup 1.0000x reference)
#include <cuda_runtime.h>
#include <math.h>
#include <float.h>

#define Bn   64
#define Tn   32
#define NEFc 256
#define Sn   289
#define Kq   16384
#define G1f  4.0f
#define G2f  5.0f
#define G3f  10.0f
#define INV_T 20.0f
#define EPSf 1e-8f

// ---------------- device scratch ----------------
__device__ float g_ctxT[Bn * Sn * NEFc];   // [j][s][c]
__device__ float g_codes[4][Bn * NEFc];    // cn, rn, can, ran
__device__ float g_simT[Bn * Bn];          // simT[j][i] = sim(i,j)
__device__ float g_Z[2][Bn * Kq];          // moco logits (already /T)
__device__ float g_MS[2][Bn][2];           // rowmax, sumexp over queue part
__device__ float g_small[2][Bn * Bn];      // G3*cn@rn^T, G3*rn@ran^T

// ---------------- K0: row-normalize code matrices ----------------
__global__ void normalize_kernel(const float* __restrict__ c0, const float* __restrict__ c1,
                                 const float* __restrict__ c2, const float* __restrict__ c3) {
    int i = blockIdx.x;
    int m = blockIdx.y;
    const float* src = (m == 0) ? c0 : (m == 1) ? c1 : (m == 2) ? c2 : c3;
    int tid = threadIdx.x;
    __shared__ float red[8];
    float v = src[i * NEFc + tid];
    float s = v * v;
    for (int o = 16; o; o >>= 1) s += __shfl_down_sync(0xffffffffu, s, o);
    if ((tid & 31) == 0) red[tid >> 5] = s;
    __syncthreads();
    float tot = 0.f;
#pragma unroll
    for (int w = 0; w < 8; w++) tot += red[w];
    g_codes[m][i * NEFc + tid] = v / fmaxf(sqrtf(tot), EPSf);
}

// ---------------- K1: transpose img_features -> ctxT[j][s][c] ----------------
__global__ void transpose_kernel(const float* __restrict__ imgf) {
    int s = blockIdx.x;
    int j = blockIdx.y;
    int c = threadIdx.x;
    g_ctxT[((size_t)j * Sn + s) * NEFc + c] = imgf[((size_t)j * NEFc + c) * Sn + s];
}

// ---------------- K2: per-(j,i) word attention similarity ----------------
#define K2_QS   (32 * 257)
#define K2_SC   (289 * 36)
#define K2_CS   (128 * 261)
#define K2_FLTS (K2_QS + K2_SC + K2_CS + 292 + 292 + 32 + 32 + 32 + 256)
#define K2_SMEM (K2_FLTS * 4)

__global__ void __launch_bounds__(256, 1)
word_pair_kernel(const float* __restrict__ imgf, const float* __restrict__ we) {
    const int j = blockIdx.x >> 6;
    const int i = blockIdx.x & 63;
    extern __shared__ float sh[];
    float* qs     = sh;                  // [32][257]
    float* sc     = qs + K2_QS;          // [289][36]
    float* cs     = sc + K2_SC;          // [128][261] / [256][33]
    float* rmax   = cs + K2_CS;
    float* rinv   = rmax + 292;
    float* qn     = rinv + 292;
    float* denomA = qn + 32;
    float* numA   = denomA + 32;
    float* wred   = numA + 32;

    const int tid  = threadIdx.x;
    const int lane = tid & 31;
    const int wid  = tid >> 5;

    for (int idx = tid; idx < Tn * NEFc; idx += 256) {
        int t = idx >> 8, c = idx & 255;
        qs[t * 257 + c] = we[((size_t)i * Tn + t) * NEFc + c];
    }
    __syncthreads();

    // qn[t]
    for (int r = 0; r < 4; r++) {
        int t = wid * 4 + r;
        float s = 0.f;
        for (int c = lane; c < NEFc; c += 32) { float v = qs[t * 257 + c]; s += v * v; }
        for (int o = 16; o; o >>= 1) s += __shfl_down_sync(0xffffffffu, s, o);
        if (lane == 0) qn[t] = sqrtf(s);
    }

    // phase 1: scores[s][t]
    const float* ctxTj = g_ctxT + (size_t)j * Sn * NEFc;
    const int tg = tid & 7;
    const int sg = tid >> 3;
    for (int s0 = 0; s0 < Sn; s0 += 128) {
        int ns = min(128, Sn - s0);
        __syncthreads();
        for (int idx = tid; idx < ns * NEFc; idx += 256) {
            int sr = idx >> 8, c = idx & 255;
            cs[sr * 261 + c] = ctxTj[(size_t)(s0 + sr) * NEFc + c];
        }
        __syncthreads();
        int srow = sg * 4;
        if (srow < ns) {
            float acc[4][4];
#pragma unroll
            for (int k = 0; k < 4; k++)
#pragma unroll
                for (int u = 0; u < 4; u++) acc[k][u] = 0.f;
            const float* csp = cs + srow * 261;
            const float* qsp = qs + (tg * 4) * 257;
#pragma unroll 4
            for (int c = 0; c < NEFc; c++) {
                float a0 = csp[c];
                float a1 = csp[261 + c];
                float a2 = csp[2 * 261 + c];
                float a3 = csp[3 * 261 + c];
                float b0 = qsp[c];
                float b1 = qsp[257 + c];
                float b2 = qsp[2 * 257 + c];
                float b3 = qsp[3 * 257 + c];
                acc[0][0] += a0 * b0; acc[0][1] += a0 * b1; acc[0][2] += a0 * b2; acc[0][3] += a0 * b3;
                acc[1][0] += a1 * b0; acc[1][1] += a1 * b1; acc[1][2] += a1 * b2; acc[1][3] += a1 * b3;
                acc[2][0] += a2 * b0; acc[2][1] += a2 * b1; acc[2][2] += a2 * b2; acc[2][3] += a2 * b3;
                acc[3][0] += a3 * b0; acc[3][1] += a3 * b1; acc[3][2] += a3 * b2; acc[3][3] += a3 * b3;
            }
#pragma unroll
            for (int k = 0; k < 4; k++) {
                if (srow + k < ns) {
                    float* dst = sc + (s0 + srow + k) * 36 + tg * 4;
                    dst[0] = acc[k][0]; dst[1] = acc[k][1]; dst[2] = acc[k][2]; dst[3] = acc[k][3];
                }
            }
        }
    }
    __syncthreads();

    // softmax over t per row s
    for (int s = tid; s < Sn; s += 256) {
        float m = -FLT_MAX;
        for (int t = 0; t < Tn; t++) m = fmaxf(m, sc[s * 36 + t]);
        float sum = 0.f;
        for (int t = 0; t < Tn; t++) sum += __expf(sc[s * 36 + t] - m);
        rmax[s] = m;
        rinv[s] = 1.f / sum;
    }
    __syncthreads();

    // softmax over s (unnormalized), num[t], replace sc with e
    for (int t = wid; t < Tn; t += 8) {
        float den = 0.f, nu = 0.f;
        for (int s = lane; s < Sn; s += 32) {
            float sv = sc[s * 36 + t];
            float a1 = __expf(sv - rmax[s]) * rinv[s];
            float e = __expf(G1f * a1);
            den += e;
            nu += e * sv;
            sc[s * 36 + t] = e;
        }
        for (int o = 16; o; o >>= 1) {
            den += __shfl_down_sync(0xffffffffu, den, o);
            nu  += __shfl_down_sync(0xffffffffu, nu, o);
        }
        if (lane == 0) { denomA[t] = den; numA[t] = nu; }
    }
    __syncthreads();

    // phase 2: wC[c][t] accumulation (c = tid)
    float wacc[32];
#pragma unroll
    for (int t = 0; t < 32; t++) wacc[t] = 0.f;
    const float* imgj = imgf + (size_t)j * NEFc * Sn;
    const int c = tid;
    for (int s0 = 0; s0 < Sn; s0 += 32) {
        int ns = min(32, Sn - s0);
        __syncthreads();
        for (int idx = tid; idx < NEFc * ns; idx += 256) {
            int cr = idx / ns, sr = idx - cr * ns;
            cs[cr * 33 + sr] = imgj[(size_t)cr * Sn + s0 + sr];
        }
        __syncthreads();
        for (int s = 0; s < ns; s++) {
            float x = cs[c * 33 + s];
            const float4* a2 = reinterpret_cast<const float4*>(sc + (s0 + s) * 36);
#pragma unroll
            for (int u = 0; u < 8; u++) {
                float4 v = a2[u];
                wacc[4 * u + 0] += x * v.x;
                wacc[4 * u + 1] += x * v.y;
                wacc[4 * u + 2] += x * v.z;
                wacc[4 * u + 3] += x * v.w;
            }
        }
    }
    __syncthreads();

#pragma unroll
    for (int t = 0; t < 32; t++) {
        float v = wacc[t] * wacc[t];
        for (int o = 16; o; o >>= 1) v += __shfl_down_sync(0xffffffffu, v, o);
        if (lane == 0) wred[wid * 32 + t] = v;
    }
    __syncthreads();

    if (tid < 32) {
        float wn2 = 0.f;
#pragma unroll
        for (int w = 0; w < 8; w++) wn2 += wred[w * 32 + tid];
        float dinv = 1.f / denomA[tid];
        float wn = sqrtf(wn2) * dinv;
        float nm = numA[tid] * dinv;
        float cosv = nm / fmaxf(qn[tid] * wn, EPSf);
        float v = G2f * cosv;
        float m = v;
        for (int o = 16; o; o >>= 1) m = fmaxf(m, __shfl_xor_sync(0xffffffffu, m, o));
        float e = __expf(v - m);
        for (int o = 16; o; o >>= 1) e += __shfl_xor_sync(0xffffffffu, e, o);
        if (tid == 0) g_simT[j * 64 + i] = logf(e) + m;
    }
}

// ---------------- K3a: moco logits GEMM ----------------
__global__ void __launch_bounds__(256) moco_gemm_kernel(const float* __restrict__ queue,
                                                        const float* __restrict__ queue_im) {
    int k0 = blockIdx.x * 128;
    int d = blockIdx.y;
    const float* A = g_codes[d];
    const float* Q = (d == 0) ? queue : queue_im;
    __shared__ float sA[64 * 33];
    __shared__ float sB[32 * 129];
    int tid = threadIdx.x;
    int rg = tid >> 4;
    int kg = tid & 15;
    float acc[4][8];
#pragma unroll
    for (int u = 0; u < 4; u++)
#pragma unroll
        for (int v = 0; v < 8; v++) acc[u][v] = 0.f;

    for (int c0 = 0; c0 < NEFc; c0 += 32) {
        __syncthreads();
        for (int idx = tid; idx < 64 * 32; idx += 256) {
            int r = idx >> 5, cc = idx & 31;
            sA[r * 33 + cc] = A[r * NEFc + c0 + cc];
        }
        for (int idx = tid; idx < 32 * 128; idx += 256) {
            int cc = idx >> 7, kk = idx & 127;
            sB[cc * 129 + kk] = Q[(size_t)(c0 + cc) * Kq + k0 + kk];
        }
        __syncthreads();
#pragma unroll 4
        for (int cc = 0; cc < 32; cc++) {
            float a0 = sA[(rg * 4 + 0) * 33 + cc];
            float a1 = sA[(rg * 4 + 1) * 33 + cc];
            float a2 = sA[(rg * 4 + 2) * 33 + cc];
            float a3 = sA[(rg * 4 + 3) * 33 + cc];
#pragma unroll
            for (int v = 0; v < 8; v++) {
                float b = sB[cc * 129 + kg + 16 * v];
                acc[0][v] += a0 * b;
                acc[1][v] += a1 * b;
                acc[2][v] += a2 * b;
                acc[3][v] += a3 * b;
            }
        }
    }
#pragma unroll
    for (int u = 0; u < 4; u++)
#pragma unroll
        for (int v = 0; v < 8; v++)
            g_Z[d][(size_t)(rg * 4 + u) * Kq + k0 + kg + 16 * v] = acc[u][v] * INV_T;
}

// ---------------- K3b: per-row logsumexp stats ----------------
__global__ void lse_kernel() {
    int i = blockIdx.x, d = blockIdx.y;
    const float* z = g_Z[d] + (size_t)i * Kq;
    int tid = threadIdx.x;
    __shared__ float red[8];
    float m = -FLT_MAX;
    for (int k = tid; k < Kq; k += 256) m = fmaxf(m, z[k]);
    for (int o = 16; o; o >>= 1) m = fmaxf(m, __shfl_xor_sync(0xffffffffu, m, o));
    if ((tid & 31) == 0) red[tid >> 5] = m;
    __syncthreads();
    float M = red[0];
#pragma unroll
    for (int w = 1; w < 8; w++) M = fmaxf(M, red[w]);
    __syncthreads();
    float s = 0.f;
    for (int k = tid; k < Kq; k += 256) s += __expf(z[k] - M);
    for (int o = 16; o; o >>= 1) s += __shfl_xor_sync(0xffffffffu, s, o);
    if ((tid & 31) == 0) red[tid >> 5] = s;
    __syncthreads();
    if (tid == 0) {
        float S = 0.f;
#pragma unroll
        for (int w = 0; w < 8; w++) S += red[w];
        g_MS[d][i][0] = M;
        g_MS[d][i][1] = S;
    }
}

// ---------------- K5: the two 64x64 code GEMMs ----------------
#define K5_SMEM (2 * 64 * 257 * 4)
__global__ void __launch_bounds__(256) pair_gemm_kernel() {
    int d = blockIdx.x;
    const float* A  = g_codes[(d == 0) ? 0 : 1];
    const float* Bm = g_codes[(d == 0) ? 1 : 3];
    extern __shared__ float sh2[];
    float* shA = sh2;
    float* shB = sh2 + 64 * 257;
    int tid = threadIdx.x;
    for (int idx = tid; idx < 64 * 256; idx += 256) {
        int r = idx >> 8, c = idx & 255;
        shA[r * 257 + c] = A[idx];
        shB[r * 257 + c] = Bm[idx];
    }
    __syncthreads();
    int rg = tid >> 4, cg = tid & 15;
    float acc[4][4];
#pragma unroll
    for (int u = 0; u < 4; u++)
#pragma unroll
        for (int v = 0; v < 4; v++) acc[u][v] = 0.f;
#pragma unroll 4
    for (int k = 0; k < 256; k++) {
        float a0 = shA[(rg * 4 + 0) * 257 + k];
        float a1 = shA[(rg * 4 + 1) * 257 + k];
        float a2 = shA[(rg * 4 + 2) * 257 + k];
        float a3 = shA[(rg * 4 + 3) * 257 + k];
        float b0 = shB[(cg * 4 + 0) * 257 + k];
        float b1 = shB[(cg * 4 + 1) * 257 + k];
        float b2 = shB[(cg * 4 + 2) * 257 + k];
        float b3 = shB[(cg * 4 + 3) * 257 + k];
        acc[0][0] += a0 * b0; acc[0][1] += a0 * b1; acc[0][2] += a0 * b2; acc[0][3] += a0 * b3;
        acc[1][0] += a1 * b0; acc[1][1] += a1 * b1; acc[1][2] += a1 * b2; acc[1][3] += a1 * b3;
        acc[2][0] += a2 * b0; acc[2][1] += a2 * b1; acc[2][2] += a2 * b2; acc[2][3] += a2 * b3;
        acc[3][0] += a3 * b0; acc[3][1] += a3 * b1; acc[3][2] += a3 * b2; acc[3][3] += a3 * b3;
    }
#pragma unroll
    for (int u = 0; u < 4; u++)
#pragma unroll
        for (int v = 0; v < 4; v++)
            g_small[d][(rg * 4 + u) * 64 + cg * 4 + v] = G3f * acc[u][v];
}

// ---------------- K4: finalize ----------------
__device__ float lse_md_row(const float* M, int r, float scale) {
    float mx = -FLT_MAX;
    for (int c2 = 0; c2 < 64; c2++) mx = fmaxf(mx, scale * M[r * 64 + c2]);
    float s = 0.f;
    for (int c2 = 0; c2 < 64; c2++) s += __expf(scale * M[r * 64 + c2] - mx);
    return logf(s) + mx - scale * M[r * 64 + r];
}
__device__ float lse_md_col(const float* M, int c2, float scale) {
    float mx = -FLT_MAX;
    for (int r = 0; r < 64; r++) mx = fmaxf(mx, scale * M[r * 64 + c2]);
    float s = 0.f;
    for (int r = 0; r < 64; r++) s += __expf(scale * M[r * 64 + c2] - mx);
    return logf(s) + mx - scale * M[c2 * 64 + c2];
}

__global__ void finalize_kernel(float* __restrict__ out) {
    __shared__ float sv[8][64];
    int tid = threadIdx.x;
    if (tid < 64) {
        int i = tid;
        sv[0][i] = lse_md_row(g_simT, i, G3f);
        sv[1][i] = lse_md_col(g_simT, i, G3f);
        sv[2][i] = lse_md_row(g_small[0], i, 1.f);
        sv[3][i] = lse_md_col(g_small[0], i, 1.f);
        sv[4][i] = lse_md_row(g_small[1], i, 1.f);
        sv[5][i] = lse_md_col(g_small[1], i, 1.f);
        float pos0 = 0.f, pos1 = 0.f;
        for (int k = 0; k < NEFc; k++) {
            pos0 += g_codes[0][i * NEFc + k] * g_codes[3][i * NEFc + k];
            pos1 += g_codes[1][i * NEFc + k] * g_codes[2][i * NEFc + k];
        }
        pos0 *= INV_T; pos1 *= INV_T;
        {
            float M = g_MS[0][i][0], S = g_MS[0][i][1];
            float Mf = fmaxf(pos0, M);
            float Sf = __expf(pos0 - Mf) + S * __expf(M - Mf);
            sv[6][i] = logf(Sf) + Mf - pos0;
        }
        {
            float M = g_MS[1][i][0], S = g_MS[1][i][1];
            float Mf = fmaxf(pos1, M);
            float Sf = __expf(pos1 - Mf) + S * __expf(M - Mf);
            sv[7][i] = logf(Sf) + Mf - pos1;
        }
    }
    __syncthreads();
    if (tid == 0) {
        float a[8];
        for (int q2 = 0; q2 < 8; q2++) {
            float s = 0.f;
            for (int k = 0; k < 64; k++) s += sv[q2][k];
            a[q2] = s * (1.f / 64.f);
        }
        out[0] = a[0];                 // w_loss0 (CE of S = simT*G3, rows=j)
        out[1] = a[1];                 // w_loss1
        out[2] = a[2];                 // loss0
        out[3] = a[3];                 // loss1
        out[4] = 0.5f * (a[6] + a[7]); // m_loss
        out[5] = a[4];                 // loss2
        out[6] = a[5];                 // loss3
    }
}

extern "C" void kernel_launch(void* const* d_in, const int* in_sizes, int n_in,
                              void* d_out, int out_size) {
    const float* cnn      = (const float*)d_in[0];
    const float* rnn      = (const float*)d_in[1];
    const float* imgf     = (const float*)d_in[2];
    const float* we       = (const float*)d_in[3];
    const float* cnn_aug  = (const float*)d_in[4];
    const float* rnn_aug  = (const float*)d_in[5];
    const float* queue    = (const float*)d_in[6];
    const float* queue_im = (const float*)d_in[7];
    float* out = (float*)d_out;

    cudaFuncSetAttribute(word_pair_kernel, cudaFuncAttributeMaxDynamicSharedMemorySize, K2_SMEM);
    cudaFuncSetAttribute(pair_gemm_kernel, cudaFuncAttributeMaxDynamicSharedMemorySize, K5_SMEM);

    normalize_kernel<<<dim3(64, 4), 256>>>(cnn, rnn, cnn_aug, rnn_aug);
    transpose_kernel<<<dim3(289, 64), 256>>>(imgf);
    word_pair_kernel<<<4096, 256, K2_SMEM>>>(imgf, we);
    moco_gemm_kernel<<<dim3(128, 2), 256>>>(queue, queue_im);
    lse_kernel<<<dim3(64, 2), 256>>>();
    pair_gemm_kernel<<<2, 256, K5_SMEM>>>();
    finalize_kernel<<<1, 256>>>(out);
}

// round 4
// speedup vs baseline: 5.8949x; 5.8949x over previous
#include <cuda_runtime.h>
#include <cuda_bf16.h>
#include <math.h>
#include <float.h>
#include <stdint.h>

#define Bn   64
#define Tn   32
#define NEFc 256
#define Sn   289
#define SPAD 384
#define Kq   16384
#define G1f  4.0f
#define G2f  5.0f
#define G3f  10.0f
#define INV_T 20.0f
#define EPSf 1e-8f

// ---------------- device scratch ----------------
__device__ uint4 g_A_hi4[64 * SPAD * 256 / 8];   // ctxT [j][s_pad][c] bf16 hi
__device__ uint4 g_A_lo4[64 * SPAD * 256 / 8];
__device__ uint4 g_X_hi4[64 * 256 * SPAD / 8];   // imgf [j][c][s_pad] bf16 hi
__device__ uint4 g_X_lo4[64 * 256 * SPAD / 8];
__device__ uint4 g_B_hi4[2048 * 256 / 8];        // we   [i*32+t][c] bf16 hi
__device__ uint4 g_B_lo4[2048 * 256 / 8];
__device__ float g_qn[2048];
__device__ float g_codes[4][Bn * NEFc];
__device__ float g_simT[Bn * Bn];
__device__ float g_Z[2][Bn * Kq];
__device__ float g_MS[2][Bn][2];
__device__ float g_small[2][Bn * Bn];

// ---------------- helpers ----------------
__device__ __forceinline__ uint32_t smem_u32(const void* p) {
    uint32_t a;
    asm("{ .reg .u64 t; cvta.to.shared.u64 t, %1; cvt.u32.u64 %0, t; }" : "=r"(a) : "l"(p));
    return a;
}
__device__ __forceinline__ void ldm_x4(uint32_t addr, uint32_t& r0, uint32_t& r1, uint32_t& r2, uint32_t& r3) {
    asm volatile("ldmatrix.sync.aligned.m8n8.x4.shared.b16 {%0,%1,%2,%3}, [%4];"
                 : "=r"(r0), "=r"(r1), "=r"(r2), "=r"(r3) : "r"(addr));
}
#define MMA16816(d, A0, A1, A2, A3, B0, B1)                                   \
    asm volatile("mma.sync.aligned.m16n8k16.row.col.f32.bf16.bf16.f32 "       \
                 "{%0,%1,%2,%3},{%4,%5,%6,%7},{%8,%9},{%0,%1,%2,%3};"          \
                 : "+f"((d)[0]), "+f"((d)[1]), "+f"((d)[2]), "+f"((d)[3])      \
                 : "r"(A0), "r"(A1), "r"(A2), "r"(A3), "r"(B0), "r"(B1))

// ---------------- prep kernels ----------------
__global__ void prep_A(const float* __restrict__ imgf) {   // grid(384,64) thr 256
    int s = blockIdx.x, j = blockIdx.y, c = threadIdx.x;
    float v = (s < Sn) ? imgf[((size_t)j * 256 + c) * Sn + s] : 0.f;
    __nv_bfloat16 hi = __float2bfloat16(v);
    __nv_bfloat16 lo = __float2bfloat16(v - __bfloat162float(hi));
    size_t o = ((size_t)j * SPAD + s) * 256 + c;
    ((__nv_bfloat16*)g_A_hi4)[o] = hi;
    ((__nv_bfloat16*)g_A_lo4)[o] = lo;
}
__global__ void prep_X(const float* __restrict__ imgf) {   // grid(256,64) thr 384
    int c = blockIdx.x, j = blockIdx.y, s = threadIdx.x;
    float v = (s < Sn) ? imgf[((size_t)j * 256 + c) * Sn + s] : 0.f;
    __nv_bfloat16 hi = __float2bfloat16(v);
    __nv_bfloat16 lo = __float2bfloat16(v - __bfloat162float(hi));
    size_t o = ((size_t)j * 256 + c) * SPAD + s;
    ((__nv_bfloat16*)g_X_hi4)[o] = hi;
    ((__nv_bfloat16*)g_X_lo4)[o] = lo;
}
__global__ void prep_B(const float* __restrict__ we) {     // grid 2048 thr 256
    int r = blockIdx.x, c = threadIdx.x;
    float v = we[(size_t)r * 256 + c];
    __nv_bfloat16 hi = __float2bfloat16(v);
    __nv_bfloat16 lo = __float2bfloat16(v - __bfloat162float(hi));
    ((__nv_bfloat16*)g_B_hi4)[(size_t)r * 256 + c] = hi;
    ((__nv_bfloat16*)g_B_lo4)[(size_t)r * 256 + c] = lo;
    __shared__ float red[8];
    float s = v * v;
    for (int o = 16; o; o >>= 1) s += __shfl_down_sync(0xffffffffu, s, o);
    if ((c & 31) == 0) red[c >> 5] = s;
    __syncthreads();
    if (c == 0) {
        float tot = 0.f;
#pragma unroll
        for (int w = 0; w < 8; w++) tot += red[w];
        g_qn[r] = sqrtf(tot);
    }
}

// ---------------- word kernel (mma.sync bf16) ----------------
// smem byte offsets
#define OFF_SC   0          // scores 320 x 65 f32 = 83200
#define OFF_XHI  0          // phase2: X chunk hi 128x136 bf16 = 34816
#define OFF_XLO  40960      //          X chunk lo
#define OFF_AHI  83200      // phase1 A chunk hi 64x264 bf16 = 33792
#define OFF_ALO  116992
#define OFF_EHI  83200      // after phase1: e 64x392 bf16 = 50176
#define OFF_WHI  150784     // we hi 64x264 = 33792
#define OFF_WLO  184576
#define OFF_DEN  218368
#define OFF_NUM  218624
#define OFF_WN2  218880
#define OFF_RMAX 219136     // 320*2 f32 = 2560
#define OFF_RINV 221696
#define WK_SMEM  224256

__global__ void __launch_bounds__(256, 1) word_mma_kernel() {
    const int j  = blockIdx.x >> 5;
    const int ip = blockIdx.x & 31;
    extern __shared__ char sm[];
    const uint32_t sb = smem_u32(sm);
    const int tid = threadIdx.x, lane = tid & 31, w = tid >> 5;

    float* scp   = (float*)(sm + OFF_SC);
    float* denA  = (float*)(sm + OFF_DEN);
    float* numA  = (float*)(sm + OFF_NUM);
    float* wn2A  = (float*)(sm + OFF_WN2);
    float* rmaxp = (float*)(sm + OFF_RMAX);
    float* rinvp = (float*)(sm + OFF_RINV);
    for (int k = tid; k < 192; k += 256) denA[k] = 0.f;  // den,num,wn2 contiguous

    // ---- load we rows (ip*64 .. +63) hi/lo into smem stride 264 ----
    for (int idx = tid; idx < 2048; idx += 256) {
        int row = idx >> 5, cb = (idx & 31) << 3;
        size_t gi = (((size_t)(ip * 64 + row)) << 5) + (idx & 31);
        *(uint4*)(sm + OFF_WHI + row * 528 + cb * 2) = g_B_hi4[gi];
        *(uint4*)(sm + OFF_WLO + row * 528 + cb * 2) = g_B_lo4[gi];
    }

    // fragment lane addressing
    const int wm = w >> 1;            // phase1: m-tile; phase2: m-tile pair
    const int wn = w & 1;             // n-tile group (4 tiles)
    const uint32_t rowA = (lane & 7) + ((lane >> 3) & 1) * 8;
    const uint32_t coffA = (lane >> 4) * 16;
    const uint32_t bRow = 32u * wn + (((uint32_t)lane >> 4) << 3) + (lane & 7);
    const uint32_t boffB = ((lane >> 3) & 1) * 16;

    // ================= phase 1: scores =================
    for (int ch = 0; ch < 5; ch++) {
        const int s0 = ch * 64;
        __syncthreads();
        for (int idx = tid; idx < 2048; idx += 256) {
            int row = idx >> 5;
            int cb8 = idx & 31;
            size_t gi = (((size_t)j * SPAD + s0 + row) << 5) + cb8;
            *(uint4*)(sm + OFF_AHI + row * 528 + cb8 * 16) = g_A_hi4[gi];
            *(uint4*)(sm + OFF_ALO + row * 528 + cb8 * 16) = g_A_lo4[gi];
        }
        __syncthreads();

        float acc[4][4];
#pragma unroll
        for (int n = 0; n < 4; n++)
#pragma unroll
            for (int r = 0; r < 4; r++) acc[n][r] = 0.f;

        const uint32_t aHi = sb + OFF_AHI + (wm * 16 + rowA) * 528 + coffA;
        const uint32_t aLo = sb + OFF_ALO + (wm * 16 + rowA) * 528 + coffA;
        const uint32_t bH0 = sb + OFF_WHI + bRow * 528 + boffB;
        const uint32_t bH1 = bH0 + 16 * 528;
        const uint32_t bL0 = sb + OFF_WLO + bRow * 528 + boffB;
        const uint32_t bL1 = bL0 + 16 * 528;

#pragma unroll 4
        for (int k = 0; k < 16; k++) {
            const uint32_t kb = (uint32_t)k * 32u;
            uint32_t a0, a1, a2, a3, l0, l1, l2, l3;
            ldm_x4(aHi + kb, a0, a1, a2, a3);
            ldm_x4(aLo + kb, l0, l1, l2, l3);
            uint32_t h00, h01, h02, h03, h10, h11, h12, h13;
            ldm_x4(bH0 + kb, h00, h01, h02, h03);
            ldm_x4(bH1 + kb, h10, h11, h12, h13);
            uint32_t q00, q01, q02, q03, q10, q11, q12, q13;
            ldm_x4(bL0 + kb, q00, q01, q02, q03);
            ldm_x4(bL1 + kb, q10, q11, q12, q13);
            // hi x hi
            MMA16816(acc[0], a0, a1, a2, a3, h00, h01);
            MMA16816(acc[1], a0, a1, a2, a3, h02, h03);
            MMA16816(acc[2], a0, a1, a2, a3, h10, h11);
            MMA16816(acc[3], a0, a1, a2, a3, h12, h13);
            // hi x lo
            MMA16816(acc[0], a0, a1, a2, a3, q00, q01);
            MMA16816(acc[1], a0, a1, a2, a3, q02, q03);
            MMA16816(acc[2], a0, a1, a2, a3, q10, q11);
            MMA16816(acc[3], a0, a1, a2, a3, q12, q13);
            // lo x hi
            MMA16816(acc[0], l0, l1, l2, l3, h00, h01);
            MMA16816(acc[1], l0, l1, l2, l3, h02, h03);
            MMA16816(acc[2], l0, l1, l2, l3, h10, h11);
            MMA16816(acc[3], l0, l1, l2, l3, h12, h13);
        }
        // dump to scores buffer
        const int rowD = s0 + wm * 16 + (lane >> 2);
#pragma unroll
        for (int n = 0; n < 4; n++) {
            const int col = (4 * wn + n) * 8 + (lane & 3) * 2;
            scp[rowD * 65 + col]           = acc[n][0];
            scp[rowD * 65 + col + 1]       = acc[n][1];
            scp[(rowD + 8) * 65 + col]     = acc[n][2];
            scp[(rowD + 8) * 65 + col + 1] = acc[n][3];
        }
    }
    __syncthreads();

    // ================= epilogue: softmaxes, den/num, e ->smem bf16 =================
    for (int r = tid; r < 320; r += 256) {
#pragma unroll
        for (int h = 0; h < 2; h++) {
            float m = -FLT_MAX;
            for (int t = 0; t < 32; t++) m = fmaxf(m, scp[r * 65 + h * 32 + t]);
            float s = 0.f;
            for (int t = 0; t < 32; t++) s += __expf(scp[r * 65 + h * 32 + t] - m);
            rmaxp[r * 2 + h] = m;
            rinvp[r * 2 + h] = 1.f / s;
        }
    }
    __syncthreads();
    {
        const int t = tid & 63, sg = tid >> 6, h = t >> 5;
        float dpart = 0.f, npart = 0.f;
        __nv_bfloat16* eP = (__nv_bfloat16*)(sm + OFF_EHI);
        for (int k2 = 0; k2 < 96; k2++) {
            const int s = sg * 96 + k2;
            float e = 0.f;
            if (s < Sn) {
                float sv = scp[s * 65 + t];
                float a1 = __expf(sv - rmaxp[s * 2 + h]) * rinvp[s * 2 + h];
                e = __expf(G1f * a1);
                dpart += e;
                npart += e * sv;
            }
            eP[t * 392 + s] = __float2bfloat16(e);
        }
        atomicAdd(&denA[t], dpart);
        atomicAdd(&numA[t], npart);
    }

    // ================= phase 2: wC = X @ e^T, wn2 =================
    for (int mt = 0; mt < 2; mt++) {
        float acc2[2][4][4];
#pragma unroll
        for (int mi = 0; mi < 2; mi++)
#pragma unroll
            for (int n = 0; n < 4; n++)
#pragma unroll
                for (int r = 0; r < 4; r++) acc2[mi][n][r] = 0.f;

        for (int sc3 = 0; sc3 < 3; sc3++) {
            __syncthreads();
            for (int idx = tid; idx < 2048; idx += 256) {
                int row = idx >> 4;
                int cb8 = idx & 15;
                size_t gi = (((size_t)(j * 256 + mt * 128 + row)) * 48) + sc3 * 16 + cb8;
                *(uint4*)(sm + OFF_XHI + row * 272 + cb8 * 16) = g_X_hi4[gi];
                *(uint4*)(sm + OFF_XLO + row * 272 + cb8 * 16) = g_X_lo4[gi];
            }
            __syncthreads();

            const uint32_t eB0 = sb + OFF_EHI + bRow * 784 + (uint32_t)sc3 * 256u + boffB;
            const uint32_t eB1 = eB0 + 16 * 784;
#pragma unroll
            for (int k = 0; k < 8; k++) {
                const uint32_t kb = (uint32_t)k * 32u;
                uint32_t e00, e01, e02, e03, e10, e11, e12, e13;
                ldm_x4(eB0 + kb, e00, e01, e02, e03);
                ldm_x4(eB1 + kb, e10, e11, e12, e13);
#pragma unroll
                for (int mi = 0; mi < 2; mi++) {
                    const uint32_t aHi = sb + OFF_XHI + ((wm * 2 + mi) * 16 + rowA) * 272 + coffA + kb;
                    const uint32_t aLo = sb + OFF_XLO + ((wm * 2 + mi) * 16 + rowA) * 272 + coffA + kb;
                    uint32_t a0, a1, a2, a3, l0, l1, l2, l3;
                    ldm_x4(aHi, a0, a1, a2, a3);
                    ldm_x4(aLo, l0, l1, l2, l3);
                    MMA16816(acc2[mi][0], a0, a1, a2, a3, e00, e01);
                    MMA16816(acc2[mi][1], a0, a1, a2, a3, e02, e03);
                    MMA16816(acc2[mi][2], a0, a1, a2, a3, e10, e11);
                    MMA16816(acc2[mi][3], a0, a1, a2, a3, e12, e13);
                    MMA16816(acc2[mi][0], l0, l1, l2, l3, e00, e01);
                    MMA16816(acc2[mi][1], l0, l1, l2, l3, e02, e03);
                    MMA16816(acc2[mi][2], l0, l1, l2, l3, e10, e11);
                    MMA16816(acc2[mi][3], l0, l1, l2, l3, e12, e13);
                }
            }
        }
        // reduce wC^2 into wn2
#pragma unroll
        for (int n = 0; n < 4; n++) {
            float v0 = 0.f, v1 = 0.f;
#pragma unroll
            for (int mi = 0; mi < 2; mi++) {
                v0 += acc2[mi][n][0] * acc2[mi][n][0] + acc2[mi][n][2] * acc2[mi][n][2];
                v1 += acc2[mi][n][1] * acc2[mi][n][1] + acc2[mi][n][3] * acc2[mi][n][3];
            }
#pragma unroll
            for (int o = 4; o <= 16; o <<= 1) {
                v0 += __shfl_xor_sync(0xffffffffu, v0, o);
                v1 += __shfl_xor_sync(0xffffffffu, v1, o);
            }
            if (lane < 4) {
                const int t = (4 * wn + n) * 8 + lane * 2;
                atomicAdd(&wn2A[t], v0);
                atomicAdd(&wn2A[t + 1], v1);
            }
        }
    }
    __syncthreads();

    // ================= finalize: cos, lse over t per sample =================
    if (tid < 64) {
        const int t = tid;
        float dinv = 1.f / denA[t];
        float wnv = sqrtf(wn2A[t]) * dinv;
        float nm = numA[t] * dinv;
        float qnv = g_qn[ip * 64 + t];
        float cosv = nm / fmaxf(qnv * wnv, EPSf);
        float v = G2f * cosv;
        float m = v;
        for (int o = 16; o; o >>= 1) m = fmaxf(m, __shfl_xor_sync(0xffffffffu, m, o));
        float e = __expf(v - m);
        for (int o = 16; o; o >>= 1) e += __shfl_xor_sync(0xffffffffu, e, o);
        if (lane == 0) g_simT[j * 64 + ip * 2 + (tid >> 5)] = logf(e) + m;
    }
}

// ---------------- normalize codes ----------------
__global__ void normalize_kernel(const float* __restrict__ c0, const float* __restrict__ c1,
                                 const float* __restrict__ c2, const float* __restrict__ c3) {
    int i = blockIdx.x;
    int m = blockIdx.y;
    const float* src = (m == 0) ? c0 : (m == 1) ? c1 : (m == 2) ? c2 : c3;
    int tid = threadIdx.x;
    __shared__ float red[8];
    float v = src[i * NEFc + tid];
    float s = v * v;
    for (int o = 16; o; o >>= 1) s += __shfl_down_sync(0xffffffffu, s, o);
    if ((tid & 31) == 0) red[tid >> 5] = s;
    __syncthreads();
    float tot = 0.f;
#pragma unroll
    for (int w = 0; w < 8; w++) tot += red[w];
    g_codes[m][i * NEFc + tid] = v / fmaxf(sqrtf(tot), EPSf);
}

// ---------------- moco logits GEMM ----------------
__global__ void __launch_bounds__(256) moco_gemm_kernel(const float* __restrict__ queue,
                                                        const float* __restrict__ queue_im) {
    int k0 = blockIdx.x * 128;
    int d = blockIdx.y;
    const float* A = g_codes[d];
    const float* Q = (d == 0) ? queue : queue_im;
    __shared__ float sA[64 * 33];
    __shared__ float sB[32 * 129];
    int tid = threadIdx.x;
    int rg = tid >> 4;
    int kg = tid & 15;
    float acc[4][8];
#pragma unroll
    for (int u = 0; u < 4; u++)
#pragma unroll
        for (int v = 0; v < 8; v++) acc[u][v] = 0.f;
    for (int c0 = 0; c0 < NEFc; c0 += 32) {
        __syncthreads();
        for (int idx = tid; idx < 64 * 32; idx += 256) {
            int r = idx >> 5, cc = idx & 31;
            sA[r * 33 + cc] = A[r * NEFc + c0 + cc];
        }
        for (int idx = tid; idx < 32 * 128; idx += 256) {
            int cc = idx >> 7, kk = idx & 127;
            sB[cc * 129 + kk] = Q[(size_t)(c0 + cc) * Kq + k0 + kk];
        }
        __syncthreads();
#pragma unroll 4
        for (int cc = 0; cc < 32; cc++) {
            float a0 = sA[(rg * 4 + 0) * 33 + cc];
            float a1 = sA[(rg * 4 + 1) * 33 + cc];
            float a2 = sA[(rg * 4 + 2) * 33 + cc];
            float a3 = sA[(rg * 4 + 3) * 33 + cc];
#pragma unroll
            for (int v = 0; v < 8; v++) {
                float b = sB[cc * 129 + kg + 16 * v];
                acc[0][v] += a0 * b;
                acc[1][v] += a1 * b;
                acc[2][v] += a2 * b;
                acc[3][v] += a3 * b;
            }
        }
    }
#pragma unroll
    for (int u = 0; u < 4; u++)
#pragma unroll
        for (int v = 0; v < 8; v++)
            g_Z[d][(size_t)(rg * 4 + u) * Kq + k0 + kg + 16 * v] = acc[u][v] * INV_T;
}

__global__ void lse_kernel() {
    int i = blockIdx.x, d = blockIdx.y;
    const float* z = g_Z[d] + (size_t)i * Kq;
    int tid = threadIdx.x;
    __shared__ float red[8];
    float m = -FLT_MAX;
    for (int k = tid; k < Kq; k += 256) m = fmaxf(m, z[k]);
    for (int o = 16; o; o >>= 1) m = fmaxf(m, __shfl_xor_sync(0xffffffffu, m, o));
    if ((tid & 31) == 0) red[tid >> 5] = m;
    __syncthreads();
    float M = red[0];
#pragma unroll
    for (int w = 1; w < 8; w++) M = fmaxf(M, red[w]);
    __syncthreads();
    float s = 0.f;
    for (int k = tid; k < Kq; k += 256) s += __expf(z[k] - M);
    for (int o = 16; o; o >>= 1) s += __shfl_xor_sync(0xffffffffu, s, o);
    if ((tid & 31) == 0) red[tid >> 5] = s;
    __syncthreads();
    if (tid == 0) {
        float S = 0.f;
#pragma unroll
        for (int w = 0; w < 8; w++) S += red[w];
        g_MS[d][i][0] = M;
        g_MS[d][i][1] = S;
    }
}

#define K5_SMEM (2 * 64 * 257 * 4)
__global__ void __launch_bounds__(256) pair_gemm_kernel() {
    int d = blockIdx.x;
    const float* A  = g_codes[(d == 0) ? 0 : 1];
    const float* Bm = g_codes[(d == 0) ? 1 : 3];
    extern __shared__ float sh2[];
    float* shA = sh2;
    float* shB = sh2 + 64 * 257;
    int tid = threadIdx.x;
    for (int idx = tid; idx < 64 * 256; idx += 256) {
        int r = idx >> 8, c = idx & 255;
        shA[r * 257 + c] = A[idx];
        shB[r * 257 + c] = Bm[idx];
    }
    __syncthreads();
    int rg = tid >> 4, cg = tid & 15;
    float acc[4][4];
#pragma unroll
    for (int u = 0; u < 4; u++)
#pragma unroll
        for (int v = 0; v < 4; v++) acc[u][v] = 0.f;
#pragma unroll 4
    for (int k = 0; k < 256; k++) {
        float a0 = shA[(rg * 4 + 0) * 257 + k];
        float a1 = shA[(rg * 4 + 1) * 257 + k];
        float a2 = shA[(rg * 4 + 2) * 257 + k];
        float a3 = shA[(rg * 4 + 3) * 257 + k];
        float b0 = shB[(cg * 4 + 0) * 257 + k];
        float b1 = shB[(cg * 4 + 1) * 257 + k];
        float b2 = shB[(cg * 4 + 2) * 257 + k];
        float b3 = shB[(cg * 4 + 3) * 257 + k];
        acc[0][0] += a0 * b0; acc[0][1] += a0 * b1; acc[0][2] += a0 * b2; acc[0][3] += a0 * b3;
        acc[1][0] += a1 * b0; acc[1][1] += a1 * b1; acc[1][2] += a1 * b2; acc[1][3] += a1 * b3;
        acc[2][0] += a2 * b0; acc[2][1] += a2 * b1; acc[2][2] += a2 * b2; acc[2][3] += a2 * b3;
        acc[3][0] += a3 * b0; acc[3][1] += a3 * b1; acc[3][2] += a3 * b2; acc[3][3] += a3 * b3;
    }
#pragma unroll
    for (int u = 0; u < 4; u++)
#pragma unroll
        for (int v = 0; v < 4; v++)
            g_small[d][(rg * 4 + u) * 64 + cg * 4 + v] = G3f * acc[u][v];
}

__device__ float lse_md_row(const float* M, int r, float scale) {
    float mx = -FLT_MAX;
    for (int c2 = 0; c2 < 64; c2++) mx = fmaxf(mx, scale * M[r * 64 + c2]);
    float s = 0.f;
    for (int c2 = 0; c2 < 64; c2++) s += __expf(scale * M[r * 64 + c2] - mx);
    return logf(s) + mx - scale * M[r * 64 + r];
}
__device__ float lse_md_col(const float* M, int c2, float scale) {
    float mx = -FLT_MAX;
    for (int r = 0; r < 64; r++) mx = fmaxf(mx, scale * M[r * 64 + c2]);
    float s = 0.f;
    for (int r = 0; r < 64; r++) s += __expf(scale * M[r * 64 + c2] - mx);
    return logf(s) + mx - scale * M[c2 * 64 + c2];
}

__global__ void finalize_kernel(float* __restrict__ out) {
    __shared__ float sv[8][64];
    int tid = threadIdx.x;
    if (tid < 64) {
        int i = tid;
        sv[0][i] = lse_md_row(g_simT, i, G3f);
        sv[1][i] = lse_md_col(g_simT, i, G3f);
        sv[2][i] = lse_md_row(g_small[0], i, 1.f);
        sv[3][i] = lse_md_col(g_small[0], i, 1.f);
        sv[4][i] = lse_md_row(g_small[1], i, 1.f);
        sv[5][i] = lse_md_col(g_small[1], i, 1.f);
        float pos0 = 0.f, pos1 = 0.f;
        for (int k = 0; k < NEFc; k++) {
            pos0 += g_codes[0][i * NEFc + k] * g_codes[3][i * NEFc + k];
            pos1 += g_codes[1][i * NEFc + k] * g_codes[2][i * NEFc + k];
        }
        pos0 *= INV_T; pos1 *= INV_T;
        {
            float M = g_MS[0][i][0], S = g_MS[0][i][1];
            float Mf = fmaxf(pos0, M);
            float Sf = __expf(pos0 - Mf) + S * __expf(M - Mf);
            sv[6][i] = logf(Sf) + Mf - pos0;
        }
        {
            float M = g_MS[1][i][0], S = g_MS[1][i][1];
            float Mf = fmaxf(pos1, M);
            float Sf = __expf(pos1 - Mf) + S * __expf(M - Mf);
            sv[7][i] = logf(Sf) + Mf - pos1;
        }
    }
    __syncthreads();
    if (tid == 0) {
        float a[8];
        for (int q2 = 0; q2 < 8; q2++) {
            float s = 0.f;
            for (int k = 0; k < 64; k++) s += sv[q2][k];
            a[q2] = s * (1.f / 64.f);
        }
        out[0] = a[0];
        out[1] = a[1];
        out[2] = a[2];
        out[3] = a[3];
        out[4] = 0.5f * (a[6] + a[7]);
        out[5] = a[4];
        out[6] = a[5];
    }
}

extern "C" void kernel_launch(void* const* d_in, const int* in_sizes, int n_in,
                              void* d_out, int out_size) {
    const float* cnn      = (const float*)d_in[0];
    const float* rnn      = (const float*)d_in[1];
    const float* imgf     = (const float*)d_in[2];
    const float* we       = (const float*)d_in[3];
    const float* cnn_aug  = (const float*)d_in[4];
    const float* rnn_aug  = (const float*)d_in[5];
    const float* queue    = (const float*)d_in[6];
    const float* queue_im = (const float*)d_in[7];
    float* out = (float*)d_out;

    cudaFuncSetAttribute(word_mma_kernel, cudaFuncAttributeMaxDynamicSharedMemorySize, WK_SMEM);
    cudaFuncSetAttribute(pair_gemm_kernel, cudaFuncAttributeMaxDynamicSharedMemorySize, K5_SMEM);

    normalize_kernel<<<dim3(64, 4), 256>>>(cnn, rnn, cnn_aug, rnn_aug);
    prep_A<<<dim3(SPAD, 64), 256>>>(imgf);
    prep_X<<<dim3(256, 64), 384>>>(imgf);
    prep_B<<<2048, 256>>>(we);
    word_mma_kernel<<<2048, 256, WK_SMEM>>>();
    moco_gemm_kernel<<<dim3(128, 2), 256>>>(queue, queue_im);
    lse_kernel<<<dim3(64, 2), 256>>>();
    pair_gemm_kernel<<<2, 256, K5_SMEM>>>();
    finalize_kernel<<<1, 256>>>(out);
}

// round 5
// speedup vs baseline: 6.0872x; 1.0326x over previous
#include <cuda_runtime.h>
#include <cuda_bf16.h>
#include <math.h>
#include <float.h>
#include <stdint.h>

#define Bn   64
#define Tn   32
#define NEFc 256
#define Sn   289
#define SPAD 384
#define Kq   16384
#define G1f  4.0f
#define G2f  5.0f
#define G3f  10.0f
#define INV_T 20.0f
#define EPSf 1e-8f

// ---------------- device scratch ----------------
__device__ uint4 g_A_hi4[64 * SPAD * 256 / 8];   // ctxT [j][s_pad][c] bf16 hi
__device__ uint4 g_A_lo4[64 * SPAD * 256 / 8];
__device__ uint4 g_X_hi4[64 * 256 * SPAD / 8];   // imgf [j][c][s_pad] bf16 hi
__device__ uint4 g_X_lo4[64 * 256 * SPAD / 8];
__device__ uint4 g_B_hi4[2048 * 256 / 8];        // we   [i*32+t][c] bf16 hi
__device__ uint4 g_B_lo4[2048 * 256 / 8];
__device__ float g_qn[2048];
__device__ float g_codes[4][Bn * NEFc];
__device__ float g_simT[Bn * Bn];
__device__ float g_Z[2][Bn * Kq];
__device__ float g_MS[2][Bn][2];
__device__ float g_small[2][Bn * Bn];

// ---------------- helpers ----------------
__device__ __forceinline__ uint32_t smem_u32(const void* p) {
    uint32_t a;
    asm("{ .reg .u64 t; cvta.to.shared.u64 t, %1; cvt.u32.u64 %0, t; }" : "=r"(a) : "l"(p));
    return a;
}
__device__ __forceinline__ void ldm_x4(uint32_t addr, uint32_t& r0, uint32_t& r1, uint32_t& r2, uint32_t& r3) {
    asm volatile("ldmatrix.sync.aligned.m8n8.x4.shared.b16 {%0,%1,%2,%3}, [%4];"
                 : "=r"(r0), "=r"(r1), "=r"(r2), "=r"(r3) : "r"(addr));
}
#define MMA16816(d, A0, A1, A2, A3, B0, B1)                                   \
    asm volatile("mma.sync.aligned.m16n8k16.row.col.f32.bf16.bf16.f32 "       \
                 "{%0,%1,%2,%3},{%4,%5,%6,%7},{%8,%9},{%0,%1,%2,%3};"          \
                 : "+f"((d)[0]), "+f"((d)[1]), "+f"((d)[2]), "+f"((d)[3])      \
                 : "r"(A0), "r"(A1), "r"(A2), "r"(A3), "r"(B0), "r"(B1))

__device__ __forceinline__ void cp16(uint32_t s, const void* g) {
    asm volatile("cp.async.ca.shared.global [%0], [%1], 16;" :: "r"(s), "l"(g));
}
#define CP_COMMIT() asm volatile("cp.async.commit_group;" ::: "memory")
#define CP_WAIT1()  asm volatile("cp.async.wait_group 1;" ::: "memory")
#define CP_WAIT0()  asm volatile("cp.async.wait_group 0;" ::: "memory")

// ---------------- prep kernels ----------------
__global__ void prep_A(const float* __restrict__ imgf) {   // grid(384,64) thr 256
    int s = blockIdx.x, j = blockIdx.y, c = threadIdx.x;
    float v = (s < Sn) ? imgf[((size_t)j * 256 + c) * Sn + s] : 0.f;
    __nv_bfloat16 hi = __float2bfloat16(v);
    __nv_bfloat16 lo = __float2bfloat16(v - __bfloat162float(hi));
    size_t o = ((size_t)j * SPAD + s) * 256 + c;
    ((__nv_bfloat16*)g_A_hi4)[o] = hi;
    ((__nv_bfloat16*)g_A_lo4)[o] = lo;
}
__global__ void prep_X(const float* __restrict__ imgf) {   // grid(256,64) thr 384
    int c = blockIdx.x, j = blockIdx.y, s = threadIdx.x;
    float v = (s < Sn) ? imgf[((size_t)j * 256 + c) * Sn + s] : 0.f;
    __nv_bfloat16 hi = __float2bfloat16(v);
    __nv_bfloat16 lo = __float2bfloat16(v - __bfloat162float(hi));
    size_t o = ((size_t)j * 256 + c) * SPAD + s;
    ((__nv_bfloat16*)g_X_hi4)[o] = hi;
    ((__nv_bfloat16*)g_X_lo4)[o] = lo;
}
__global__ void prep_B(const float* __restrict__ we) {     // grid 2048 thr 256
    int r = blockIdx.x, c = threadIdx.x;
    float v = we[(size_t)r * 256 + c];
    __nv_bfloat16 hi = __float2bfloat16(v);
    __nv_bfloat16 lo = __float2bfloat16(v - __bfloat162float(hi));
    ((__nv_bfloat16*)g_B_hi4)[(size_t)r * 256 + c] = hi;
    ((__nv_bfloat16*)g_B_lo4)[(size_t)r * 256 + c] = lo;
    __shared__ float red[8];
    float s = v * v;
    for (int o = 16; o; o >>= 1) s += __shfl_down_sync(0xffffffffu, s, o);
    if ((c & 31) == 0) red[c >> 5] = s;
    __syncthreads();
    if (c == 0) {
        float tot = 0.f;
#pragma unroll
        for (int w = 0; w < 8; w++) tot += red[w];
        g_qn[r] = sqrtf(tot);
    }
}

// ---------------- word kernel smem layout (bytes) ----------------
// phase1: scores @0 (83200) | Whi @83200 | Wlo @116992 | Abuf0 @150784 | Abuf1 @184576
// phase2: Xbuf0 @0 (69632)  | Xbuf1 @69632 | e @150784 (50176)
// stats:  @218368 den(256) num(256) wn2(256) rmax(2560) rinv(2560) -> 224256
#define OFF_SC   0
#define OFF_WHI  83200
#define OFF_WLO  116992
#define OFF_AB0  150784
#define OFF_AB1  184576
#define A_LOOFF  16896
#define OFF_XB0  0
#define OFF_XB1  69632
#define X_LOOFF  34816
#define OFF_E    150784
#define OFF_DEN  218368
#define OFF_NUM  218624
#define OFF_WN2  218880
#define OFF_RMAX 219136
#define OFF_RINV 221696
#define WK_SMEM  224256

__global__ void __launch_bounds__(256, 1) word_mma_kernel() {
    const int j  = blockIdx.x >> 5;
    const int ip = blockIdx.x & 31;
    extern __shared__ char sm[];
    const uint32_t sb = smem_u32(sm);
    const int tid = threadIdx.x, lane = tid & 31, w = tid >> 5;

    float* scp   = (float*)(sm + OFF_SC);
    float* denA  = (float*)(sm + OFF_DEN);
    float* numA  = (float*)(sm + OFF_NUM);
    float* wn2A  = (float*)(sm + OFF_WN2);
    float* rmaxp = (float*)(sm + OFF_RMAX);
    float* rinvp = (float*)(sm + OFF_RINV);
    for (int k = tid; k < 192; k += 256) denA[k] = 0.f;  // den,num,wn2 contiguous

    // ---- prologue: async-load W (hi+lo) and A chunk 0 ----
    {
        // W: 64 rows x 32 cb16, hi+lo = 4096 ops
        for (int idx = tid; idx < 4096; idx += 256) {
            int m = idx >> 11, r = (idx >> 5) & 63, cb = idx & 31;
            const uint4* src = (m ? g_B_lo4 : g_B_hi4) + (((size_t)(ip * 64 + r)) << 5) + cb;
            cp16(sb + (m ? OFF_WLO : OFF_WHI) + r * 528 + cb * 16, src);
        }
        // A chunk 0: 32 rows x 32 cb16, hi+lo = 2048 ops
        for (int idx = tid; idx < 2048; idx += 256) {
            int m = idx >> 10, r = (idx >> 5) & 31, cb = idx & 31;
            const uint4* src = (m ? g_A_lo4 : g_A_hi4) + (((size_t)j * SPAD + r) << 5) + cb;
            cp16(sb + OFF_AB0 + m * A_LOOFF + r * 528 + cb * 16, src);
        }
        CP_COMMIT();
    }

    // fragment lane addressing
    const int wm1 = w >> 2;          // phase1 m-tile (2 tiles of 16 over 32-row chunk)
    const int wn1 = w & 3;           // phase1 n-group (4 groups of 16 t)
    const uint32_t rowA = (lane & 7) + ((lane >> 3) & 1) * 8;
    const uint32_t coffA = (lane >> 4) * 16;
    const uint32_t bRow1 = 16u * wn1 + (((uint32_t)lane >> 4) << 3) + (lane & 7);
    const uint32_t boffB = ((lane >> 3) & 1) * 16;

    // ================= phase 1: scores (10 chunks of 32 s-rows, pipelined) =================
    for (int ch = 0; ch < 10; ch++) {
        if (ch + 1 < 10) {
            uint32_t dst = sb + ((ch + 1) & 1 ? OFF_AB1 : OFF_AB0);
            for (int idx = tid; idx < 2048; idx += 256) {
                int m = idx >> 10, r = (idx >> 5) & 31, cb = idx & 31;
                const uint4* src = (m ? g_A_lo4 : g_A_hi4) + (((size_t)j * SPAD + (ch + 1) * 32 + r) << 5) + cb;
                cp16(dst + m * A_LOOFF + r * 528 + cb * 16, src);
            }
            CP_COMMIT();
            CP_WAIT1();
        } else {
            CP_WAIT0();
        }
        __syncthreads();

        const uint32_t ab = sb + (ch & 1 ? OFF_AB1 : OFF_AB0);
        float acc[2][4];
#pragma unroll
        for (int n = 0; n < 2; n++)
#pragma unroll
            for (int r = 0; r < 4; r++) acc[n][r] = 0.f;

        const uint32_t aHi = ab + (wm1 * 16 + rowA) * 528 + coffA;
        const uint32_t aLo = aHi + A_LOOFF;
        const uint32_t bHi = sb + OFF_WHI + bRow1 * 528 + boffB;
        const uint32_t bLo = sb + OFF_WLO + bRow1 * 528 + boffB;

#pragma unroll 4
        for (int k = 0; k < 16; k++) {
            const uint32_t kb = (uint32_t)k * 32u;
            uint32_t a0, a1, a2, a3, l0, l1, l2, l3;
            ldm_x4(aHi + kb, a0, a1, a2, a3);
            ldm_x4(aLo + kb, l0, l1, l2, l3);
            uint32_t h0, h1, h2, h3, q0, q1, q2, q3;
            ldm_x4(bHi + kb, h0, h1, h2, h3);
            ldm_x4(bLo + kb, q0, q1, q2, q3);
            MMA16816(acc[0], a0, a1, a2, a3, h0, h1);
            MMA16816(acc[1], a0, a1, a2, a3, h2, h3);
            MMA16816(acc[0], a0, a1, a2, a3, q0, q1);
            MMA16816(acc[1], a0, a1, a2, a3, q2, q3);
            MMA16816(acc[0], l0, l1, l2, l3, h0, h1);
            MMA16816(acc[1], l0, l1, l2, l3, h2, h3);
        }
        const int rowD = ch * 32 + wm1 * 16 + (lane >> 2);
#pragma unroll
        for (int n = 0; n < 2; n++) {
            const int col = (2 * wn1 + n) * 8 + (lane & 3) * 2;
            scp[rowD * 65 + col]           = acc[n][0];
            scp[rowD * 65 + col + 1]       = acc[n][1];
            scp[(rowD + 8) * 65 + col]     = acc[n][2];
            scp[(rowD + 8) * 65 + col + 1] = acc[n][3];
        }
        __syncthreads();
    }

    // ================= epilogue: softmaxes, den/num, e -> smem bf16 =================
    for (int r = tid; r < 320; r += 256) {
#pragma unroll
        for (int h = 0; h < 2; h++) {
            float m = -FLT_MAX;
            for (int t = 0; t < 32; t++) m = fmaxf(m, scp[r * 65 + h * 32 + t]);
            float s = 0.f;
            for (int t = 0; t < 32; t++) s += __expf(scp[r * 65 + h * 32 + t] - m);
            rmaxp[r * 2 + h] = m;
            rinvp[r * 2 + h] = 1.f / s;
        }
    }
    __syncthreads();
    {
        const int t = tid & 63, sg = tid >> 6, h = t >> 5;
        float dpart = 0.f, npart = 0.f;
        __nv_bfloat16* eP = (__nv_bfloat16*)(sm + OFF_E);
        for (int k2 = 0; k2 < 96; k2++) {
            const int s = sg * 96 + k2;
            float e = 0.f;
            if (s < Sn) {
                float sv = scp[s * 65 + t];
                float a1 = __expf(sv - rmaxp[s * 2 + h]) * rinvp[s * 2 + h];
                e = __expf(G1f * a1);
                dpart += e;
                npart += e * sv;
            }
            eP[t * 392 + s] = __float2bfloat16(e);
        }
        atomicAdd(&denA[t], dpart);
        atomicAdd(&numA[t], npart);
    }
    __syncthreads();   // scores fully consumed; X buffers may overwrite them

    // ================= phase 2: wC = X @ e^T (6 chunks, pipelined) =================
    const int wm2 = w >> 1;   // 4 m-tiles of 16 over 128-row chunk
    const int wn2 = w & 1;    // 2 n-groups of 32 t
    const uint32_t bRow2 = 32u * wn2 + (((uint32_t)lane >> 4) << 3) + (lane & 7);

    // issue chunk 0
    for (int idx = tid; idx < 4096; idx += 256) {
        int m = idx >> 11, r = (idx >> 4) & 127, cb = idx & 15;
        const uint4* src = (m ? g_X_lo4 : g_X_hi4) + (((size_t)(j * 256 + r)) * 48) + cb;
        cp16(sb + OFF_XB0 + m * X_LOOFF + r * 272 + cb * 16, src);
    }
    CP_COMMIT();

    float acc2[2][4][4];
    for (int q = 0; q < 6; q++) {
        const int mt = q / 3, sc3 = q % 3;
        if (q + 1 < 6) {
            const int mtn = (q + 1) / 3, sc3n = (q + 1) % 3;
            uint32_t dst = sb + ((q + 1) & 1 ? OFF_XB1 : OFF_XB0);
            for (int idx = tid; idx < 4096; idx += 256) {
                int m = idx >> 11, r = (idx >> 4) & 127, cb = idx & 15;
                const uint4* src = (m ? g_X_lo4 : g_X_hi4) +
                                   (((size_t)(j * 256 + mtn * 128 + r)) * 48) + sc3n * 16 + cb;
                cp16(dst + m * X_LOOFF + r * 272 + cb * 16, src);
            }
            CP_COMMIT();
            CP_WAIT1();
        } else {
            CP_WAIT0();
        }
        __syncthreads();

        if (sc3 == 0) {
#pragma unroll
            for (int mi = 0; mi < 2; mi++)
#pragma unroll
                for (int n = 0; n < 4; n++)
#pragma unroll
                    for (int r = 0; r < 4; r++) acc2[mi][n][r] = 0.f;
        }

        const uint32_t xb = sb + (q & 1 ? OFF_XB1 : OFF_XB0);
        const uint32_t eB0 = sb + OFF_E + bRow2 * 784 + (uint32_t)sc3 * 256u + boffB;
        const uint32_t eB1 = eB0 + 16 * 784;
#pragma unroll
        for (int k = 0; k < 8; k++) {
            const uint32_t kb = (uint32_t)k * 32u;
            uint32_t e00, e01, e02, e03, e10, e11, e12, e13;
            ldm_x4(eB0 + kb, e00, e01, e02, e03);
            ldm_x4(eB1 + kb, e10, e11, e12, e13);
#pragma unroll
            for (int mi = 0; mi < 2; mi++) {
                const uint32_t aHi2 = xb + ((wm2 * 2 + mi) * 16 + rowA) * 272 + coffA + kb;
                const uint32_t aLo2 = aHi2 + X_LOOFF;
                uint32_t a0, a1, a2, a3, l0, l1, l2, l3;
                ldm_x4(aHi2, a0, a1, a2, a3);
                ldm_x4(aLo2, l0, l1, l2, l3);
                MMA16816(acc2[mi][0], a0, a1, a2, a3, e00, e01);
                MMA16816(acc2[mi][1], a0, a1, a2, a3, e02, e03);
                MMA16816(acc2[mi][2], a0, a1, a2, a3, e10, e11);
                MMA16816(acc2[mi][3], a0, a1, a2, a3, e12, e13);
                MMA16816(acc2[mi][0], l0, l1, l2, l3, e00, e01);
                MMA16816(acc2[mi][1], l0, l1, l2, l3, e02, e03);
                MMA16816(acc2[mi][2], l0, l1, l2, l3, e10, e11);
                MMA16816(acc2[mi][3], l0, l1, l2, l3, e12, e13);
            }
        }
        __syncthreads();

        if (sc3 == 2) {
            // reduce wC^2 into wn2
#pragma unroll
            for (int n = 0; n < 4; n++) {
                float v0 = 0.f, v1 = 0.f;
#pragma unroll
                for (int mi = 0; mi < 2; mi++) {
                    v0 += acc2[mi][n][0] * acc2[mi][n][0] + acc2[mi][n][2] * acc2[mi][n][2];
                    v1 += acc2[mi][n][1] * acc2[mi][n][1] + acc2[mi][n][3] * acc2[mi][n][3];
                }
#pragma unroll
                for (int o = 4; o <= 16; o <<= 1) {
                    v0 += __shfl_xor_sync(0xffffffffu, v0, o);
                    v1 += __shfl_xor_sync(0xffffffffu, v1, o);
                }
                if (lane < 4) {
                    const int t = (4 * wn2 + n) * 8 + lane * 2;
                    atomicAdd(&wn2A[t], v0);
                    atomicAdd(&wn2A[t + 1], v1);
                }
            }
        }
    }
    __syncthreads();

    // ================= finalize: cos, lse over t per sample =================
    if (tid < 64) {
        const int t = tid;
        float dinv = 1.f / denA[t];
        float wnv = sqrtf(wn2A[t]) * dinv;
        float nm = numA[t] * dinv;
        float qnv = g_qn[ip * 64 + t];
        float cosv = nm / fmaxf(qnv * wnv, EPSf);
        float v = G2f * cosv;
        float m = v;
        for (int o = 16; o; o >>= 1) m = fmaxf(m, __shfl_xor_sync(0xffffffffu, m, o));
        float e = __expf(v - m);
        for (int o = 16; o; o >>= 1) e += __shfl_xor_sync(0xffffffffu, e, o);
        if (lane == 0) g_simT[j * 64 + ip * 2 + (tid >> 5)] = logf(e) + m;
    }
}

// ---------------- normalize codes ----------------
__global__ void normalize_kernel(const float* __restrict__ c0, const float* __restrict__ c1,
                                 const float* __restrict__ c2, const float* __restrict__ c3) {
    int i = blockIdx.x;
    int m = blockIdx.y;
    const float* src = (m == 0) ? c0 : (m == 1) ? c1 : (m == 2) ? c2 : c3;
    int tid = threadIdx.x;
    __shared__ float red[8];
    float v = src[i * NEFc + tid];
    float s = v * v;
    for (int o = 16; o; o >>= 1) s += __shfl_down_sync(0xffffffffu, s, o);
    if ((tid & 31) == 0) red[tid >> 5] = s;
    __syncthreads();
    float tot = 0.f;
#pragma unroll
    for (int w = 0; w < 8; w++) tot += red[w];
    g_codes[m][i * NEFc + tid] = v / fmaxf(sqrtf(tot), EPSf);
}

// ---------------- moco logits GEMM (512 blocks, k-tile 64) ----------------
__global__ void __launch_bounds__(256) moco_gemm_kernel(const float* __restrict__ queue,
                                                        const float* __restrict__ queue_im) {
    int k0 = blockIdx.x * 64;
    int d = blockIdx.y;
    const float* A = g_codes[d];
    const float* Q = (d == 0) ? queue : queue_im;
    __shared__ float sA[64 * 33];
    __shared__ float sB[32 * 65];
    int tid = threadIdx.x;
    int rg = tid >> 4;
    int kg = tid & 15;
    float acc[4][4];
#pragma unroll
    for (int u = 0; u < 4; u++)
#pragma unroll
        for (int v = 0; v < 4; v++) acc[u][v] = 0.f;
    for (int c0 = 0; c0 < NEFc; c0 += 32) {
        __syncthreads();
        for (int idx = tid; idx < 64 * 32; idx += 256) {
            int r = idx >> 5, cc = idx & 31;
            sA[r * 33 + cc] = A[r * NEFc + c0 + cc];
        }
        for (int idx = tid; idx < 32 * 64; idx += 256) {
            int cc = idx >> 6, kk = idx & 63;
            sB[cc * 65 + kk] = Q[(size_t)(c0 + cc) * Kq + k0 + kk];
        }
        __syncthreads();
#pragma unroll 4
        for (int cc = 0; cc < 32; cc++) {
            float a0 = sA[(rg * 4 + 0) * 33 + cc];
            float a1 = sA[(rg * 4 + 1) * 33 + cc];
            float a2 = sA[(rg * 4 + 2) * 33 + cc];
            float a3 = sA[(rg * 4 + 3) * 33 + cc];
#pragma unroll
            for (int v = 0; v < 4; v++) {
                float b = sB[cc * 65 + kg + 16 * v];
                acc[0][v] += a0 * b;
                acc[1][v] += a1 * b;
                acc[2][v] += a2 * b;
                acc[3][v] += a3 * b;
            }
        }
    }
#pragma unroll
    for (int u = 0; u < 4; u++)
#pragma unroll
        for (int v = 0; v < 4; v++)
            g_Z[d][(size_t)(rg * 4 + u) * Kq + k0 + kg + 16 * v] = acc[u][v] * INV_T;
}

__global__ void lse_kernel() {
    int i = blockIdx.x, d = blockIdx.y;
    const float* z = g_Z[d] + (size_t)i * Kq;
    int tid = threadIdx.x;
    __shared__ float red[8];
    float m = -FLT_MAX;
    for (int k = tid; k < Kq; k += 256) m = fmaxf(m, z[k]);
    for (int o = 16; o; o >>= 1) m = fmaxf(m, __shfl_xor_sync(0xffffffffu, m, o));
    if ((tid & 31) == 0) red[tid >> 5] = m;
    __syncthreads();
    float M = red[0];
#pragma unroll
    for (int w = 1; w < 8; w++) M = fmaxf(M, red[w]);
    __syncthreads();
    float s = 0.f;
    for (int k = tid; k < Kq; k += 256) s += __expf(z[k] - M);
    for (int o = 16; o; o >>= 1) s += __shfl_xor_sync(0xffffffffu, s, o);
    if ((tid & 31) == 0) red[tid >> 5] = s;
    __syncthreads();
    if (tid == 0) {
        float S = 0.f;
#pragma unroll
        for (int w = 0; w < 8; w++) S += red[w];
        g_MS[d][i][0] = M;
        g_MS[d][i][1] = S;
    }
}

#define K5_SMEM (2 * 64 * 257 * 4)
__global__ void __launch_bounds__(256) pair_gemm_kernel() {
    int d = blockIdx.x;
    const float* A  = g_codes[(d == 0) ? 0 : 1];
    const float* Bm = g_codes[(d == 0) ? 1 : 3];
    extern __shared__ float sh2[];
    float* shA = sh2;
    float* shB = sh2 + 64 * 257;
    int tid = threadIdx.x;
    for (int idx = tid; idx < 64 * 256; idx += 256) {
        int r = idx >> 8, c = idx & 255;
        shA[r * 257 + c] = A[idx];
        shB[r * 257 + c] = Bm[idx];
    }
    __syncthreads();
    int rg = tid >> 4, cg = tid & 15;
    float acc[4][4];
#pragma unroll
    for (int u = 0; u < 4; u++)
#pragma unroll
        for (int v = 0; v < 4; v++) acc[u][v] = 0.f;
#pragma unroll 4
    for (int k = 0; k < 256; k++) {
        float a0 = shA[(rg * 4 + 0) * 257 + k];
        float a1 = shA[(rg * 4 + 1) * 257 + k];
        float a2 = shA[(rg * 4 + 2) * 257 + k];
        float a3 = shA[(rg * 4 + 3) * 257 + k];
        float b0 = shB[(cg * 4 + 0) * 257 + k];
        float b1 = shB[(cg * 4 + 1) * 257 + k];
        float b2 = shB[(cg * 4 + 2) * 257 + k];
        float b3 = shB[(cg * 4 + 3) * 257 + k];
        acc[0][0] += a0 * b0; acc[0][1] += a0 * b1; acc[0][2] += a0 * b2; acc[0][3] += a0 * b3;
        acc[1][0] += a1 * b0; acc[1][1] += a1 * b1; acc[1][2] += a1 * b2; acc[1][3] += a1 * b3;
        acc[2][0] += a2 * b0; acc[2][1] += a2 * b1; acc[2][2] += a2 * b2; acc[2][3] += a2 * b3;
        acc[3][0] += a3 * b0; acc[3][1] += a3 * b1; acc[3][2] += a3 * b2; acc[3][3] += a3 * b3;
    }
#pragma unroll
    for (int u = 0; u < 4; u++)
#pragma unroll
        for (int v = 0; v < 4; v++)
            g_small[d][(rg * 4 + u) * 64 + cg * 4 + v] = G3f * acc[u][v];
}

__device__ float lse_md_row(const float* M, int r, float scale) {
    float mx = -FLT_MAX;
    for (int c2 = 0; c2 < 64; c2++) mx = fmaxf(mx, scale * M[r * 64 + c2]);
    float s = 0.f;
    for (int c2 = 0; c2 < 64; c2++) s += __expf(scale * M[r * 64 + c2] - mx);
    return logf(s) + mx - scale * M[r * 64 + r];
}
__device__ float lse_md_col(const float* M, int c2, float scale) {
    float mx = -FLT_MAX;
    for (int r = 0; r < 64; r++) mx = fmaxf(mx, scale * M[r * 64 + c2]);
    float s = 0.f;
    for (int r = 0; r < 64; r++) s += __expf(scale * M[r * 64 + c2] - mx);
    return logf(s) + mx - scale * M[c2 * 64 + c2];
}

__global__ void finalize_kernel(float* __restrict__ out) {
    __shared__ float sv[8][64];
    int tid = threadIdx.x;
    if (tid < 64) {
        int i = tid;
        sv[0][i] = lse_md_row(g_simT, i, G3f);
        sv[1][i] = lse_md_col(g_simT, i, G3f);
        sv[2][i] = lse_md_row(g_small[0], i, 1.f);
        sv[3][i] = lse_md_col(g_small[0], i, 1.f);
        sv[4][i] = lse_md_row(g_small[1], i, 1.f);
        sv[5][i] = lse_md_col(g_small[1], i, 1.f);
        float pos0 = 0.f, pos1 = 0.f;
        for (int k = 0; k < NEFc; k++) {
            pos0 += g_codes[0][i * NEFc + k] * g_codes[3][i * NEFc + k];
            pos1 += g_codes[1][i * NEFc + k] * g_codes[2][i * NEFc + k];
        }
        pos0 *= INV_T; pos1 *= INV_T;
        {
            float M = g_MS[0][i][0], S = g_MS[0][i][1];
            float Mf = fmaxf(pos0, M);
            float Sf = __expf(pos0 - Mf) + S * __expf(M - Mf);
            sv[6][i] = logf(Sf) + Mf - pos0;
        }
        {
            float M = g_MS[1][i][0], S = g_MS[1][i][1];
            float Mf = fmaxf(pos1, M);
            float Sf = __expf(pos1 - Mf) + S * __expf(M - Mf);
            sv[7][i] = logf(Sf) + Mf - pos1;
        }
    }
    __syncthreads();
    if (tid == 0) {
        float a[8];
        for (int q2 = 0; q2 < 8; q2++) {
            float s = 0.f;
            for (int k = 0; k < 64; k++) s += sv[q2][k];
            a[q2] = s * (1.f / 64.f);
        }
        out[0] = a[0];
        out[1] = a[1];
        out[2] = a[2];
        out[3] = a[3];
        out[4] = 0.5f * (a[6] + a[7]);
        out[5] = a[4];
        out[6] = a[5];
    }
}

extern "C" void kernel_launch(void* const* d_in, const int* in_sizes, int n_in,
                              void* d_out, int out_size) {
    const float* cnn      = (const float*)d_in[0];
    const float* rnn      = (const float*)d_in[1];
    const float* imgf     = (const float*)d_in[2];
    const float* we       = (const float*)d_in[3];
    const float* cnn_aug  = (const float*)d_in[4];
    const float* rnn_aug  = (const float*)d_in[5];
    const float* queue    = (const float*)d_in[6];
    const float* queue_im = (const float*)d_in[7];
    float* out = (float*)d_out;

    cudaFuncSetAttribute(word_mma_kernel, cudaFuncAttributeMaxDynamicSharedMemorySize, WK_SMEM);
    cudaFuncSetAttribute(pair_gemm_kernel, cudaFuncAttributeMaxDynamicSharedMemorySize, K5_SMEM);

    normalize_kernel<<<dim3(64, 4), 256>>>(cnn, rnn, cnn_aug, rnn_aug);
    prep_A<<<dim3(SPAD, 64), 256>>>(imgf);
    prep_X<<<dim3(256, 64), 384>>>(imgf);
    prep_B<<<2048, 256>>>(we);
    word_mma_kernel<<<2048, 256, WK_SMEM>>>();
    moco_gemm_kernel<<<dim3(256, 2), 256>>>(queue, queue_im);
    lse_kernel<<<dim3(64, 2), 256>>>();
    pair_gemm_kernel<<<2, 256, K5_SMEM>>>();
    finalize_kernel<<<1, 256>>>(out);
}